// round 14
// baseline (speedup 1.0000x reference)
#include <cuda_runtime.h>
#include <cuda_fp16.h>
#include <stdint.h>

#define Tc  2048
#define Dc  1024
#define Hc  16
#define BHc 32
#define GBH 16                // heads per pipeline group (= one batch)

// ---------------- static device scratch ----------------
__device__ __half g_Xin[3u * 4194304];        // q,k,v fp16 (slot 0 reused for O)
__device__ __half g_Wall[4u * 1048576];       // Wq,Wk,Wv,Wc fp16
__device__ __half g_QH[BHc * Tc * 64];        // [bh][t][nd]
__device__ __half g_KH[BHc * Tc * 64];
__device__ float  g_V [BHc * Tc * 64];        // V heads fp32
__device__ __half g_VT[BHc * 64 * Tc];        // [bh][d][k], scaled by inv[k]
__device__ float  g_part[BHc * 16 * Tc];      // per-(bh,qt) column partials
__device__ __half g_E[(size_t)BHc * Tc * Tc]; // exp(z), fp16, lower tile-band

// ---------------- streams/events (host objects; created pre-main) ----------
namespace {
struct SideStream {
  cudaStream_t s1 = nullptr;
  cudaEvent_t evA = nullptr, evV = nullptr, evSA = nullptr, evB = nullptr;
  SideStream() {
    cudaStreamCreateWithFlags(&s1, cudaStreamNonBlocking);
    cudaEventCreateWithFlags(&evA,  cudaEventDisableTiming);
    cudaEventCreateWithFlags(&evV,  cudaEventDisableTiming);
    cudaEventCreateWithFlags(&evSA, cudaEventDisableTiming);
    cudaEventCreateWithFlags(&evB,  cudaEventDisableTiming);
  }
};
SideStream g_ss;
}

// ---------------- warp MMA / async helpers ----------------
static __device__ __forceinline__ void mma16816(float* d, const uint32_t* a,
                                                const uint32_t* b) {
  asm volatile(
    "mma.sync.aligned.m16n8k16.row.col.f32.f16.f16.f32 "
    "{%0,%1,%2,%3}, {%4,%5,%6,%7}, {%8,%9}, {%0,%1,%2,%3};"
    : "+f"(d[0]), "+f"(d[1]), "+f"(d[2]), "+f"(d[3])
    : "r"(a[0]), "r"(a[1]), "r"(a[2]), "r"(a[3]), "r"(b[0]), "r"(b[1]));
}
static __device__ __forceinline__ void ldsm4(uint32_t* r, const void* p) {
  uint32_t a = (uint32_t)__cvta_generic_to_shared(p);
  asm volatile("ldmatrix.sync.aligned.m8n8.x4.shared.b16 {%0,%1,%2,%3}, [%4];"
               : "=r"(r[0]), "=r"(r[1]), "=r"(r[2]), "=r"(r[3]) : "r"(a));
}
static __device__ __forceinline__ void cpa16(void* s, const void* g) {
  uint32_t a = (uint32_t)__cvta_generic_to_shared(s);
  asm volatile("cp.async.cg.shared.global [%0], [%1], 16;" :: "r"(a), "l"(g));
}
#define CP_COMMIT() asm volatile("cp.async.commit_group;" ::: "memory")
#define CP_WAIT1()  asm volatile("cp.async.wait_group 1;" ::: "memory")
#define CP_WAIT0()  asm volatile("cp.async.wait_group 0;" ::: "memory")

// ---------------- one-shot fp32 -> fp16 for all inputs + weights ------------
__global__ __launch_bounds__(256)
void cvt_all(const float* __restrict__ q, const float* __restrict__ k,
             const float* __restrict__ v, const float* __restrict__ Wq,
             const float* __restrict__ Wk, const float* __restrict__ Wv,
             const float* __restrict__ Wc)
{
  size_t t8 = ((size_t)blockIdx.x * 256 + threadIdx.x) * 8;
  const float* src; __half* dst;
  if (t8 < (3ull << 22)) {
    int i = (int)(t8 >> 22); size_t off = t8 & ((1ull << 22) - 1);
    src = (i == 0 ? q : i == 1 ? k : v) + off;
    dst = g_Xin + ((size_t)i << 22) + off;
  } else {
    size_t r = t8 - (3ull << 22);
    int w = (int)(r >> 20); size_t off = r & ((1ull << 20) - 1);
    src = (w == 0 ? Wq : w == 1 ? Wk : w == 2 ? Wv : Wc) + off;
    dst = g_Wall + ((size_t)w << 20) + off;
  }
  float4 a = *(const float4*)(src);
  float4 b = *(const float4*)(src + 4);
  __half2 h0 = __floats2half2_rn(a.x, a.y), h1 = __floats2half2_rn(a.z, a.w);
  __half2 h2 = __floats2half2_rn(b.x, b.y), h3 = __floats2half2_rn(b.z, b.w);
  uint4 u;
  u.x = *(uint32_t*)&h0; u.y = *(uint32_t*)&h1;
  u.z = *(uint32_t*)&h2; u.w = *(uint32_t*)&h3;
  *(uint4*)dst = u;
}

// ---------------- projection GEMM: Y = X @ W^T + b --------------------------
#define PSTG (128*40 + 128*40)            // halves per stage: 10240
__global__ __launch_bounds__(256, 2)
void proj_tc(const __half* __restrict__ Xbase, const __half* __restrict__ Wbase,
             const float* __restrict__ b0, const float* __restrict__ b1,
             int mode0, float* __restrict__ outp)
{
  extern __shared__ __align__(16) __half psm[];
  const int tid = threadIdx.x, lane = tid & 31, wid = tid >> 5;
  const int bn = blockIdx.x * 128, bm = blockIdx.y * 128;
  const int wm = (wid >> 2) * 64, wn = (wid & 3) * 32;

  const int z = blockIdx.z;
  const int mode = mode0 ? mode0 + z : 0;
  const __half* X = Xbase + ((size_t)z << 22);
  const __half* W = Wbase + ((size_t)z << 20);
  const float* bias = z ? b1 : b0;

  const int lr = tid >> 2, lc = tid & 3;

  #define PLOAD(st, kb) do {                                                   \
    __half (*As_)[40] = (__half(*)[40])(psm + (st) * PSTG);                    \
    __half (*Bs_)[40] = (__half(*)[40])(psm + (st) * PSTG + 128*40);           \
    _Pragma("unroll")                                                          \
    for (int i_ = 0; i_ < 2; i_++) {                                           \
      cpa16(&As_[lr + i_*64][lc*8], X + (size_t)(bm + lr + i_*64)*1024 + (kb) + lc*8); \
      cpa16(&Bs_[lr + i_*64][lc*8], W + (size_t)(bn + lr + i_*64)*1024 + (kb) + lc*8); \
    }                                                                          \
    CP_COMMIT();                                                               \
  } while (0)

  PLOAD(0, 0);
  PLOAD(1, 32);

  float acc[4][4][4] = {};
  for (int ch = 0; ch < 32; ch++) {
    if (ch + 1 < 32) CP_WAIT1(); else CP_WAIT0();
    __syncthreads();
    if (ch + 2 < 32) PLOAD((ch + 2) % 3, (ch + 2) * 32);
    __half (*As)[40] = (__half(*)[40])(psm + (ch % 3) * PSTG);
    __half (*Bs)[40] = (__half(*)[40])(psm + (ch % 3) * PSTG + 128*40);
    #pragma unroll
    for (int k16 = 0; k16 < 2; k16++) {
      uint32_t aF[4][4], bF[2][4];
      #pragma unroll
      for (int mf = 0; mf < 4; mf++)
        ldsm4(aF[mf], &As[wm + mf * 16 + (lane & 15)][k16 * 16 + (lane >> 4) * 8]);
      #pragma unroll
      for (int nh = 0; nh < 2; nh++)
        ldsm4(bF[nh], &Bs[wn + nh * 16 + (lane & 15)][k16 * 16 + (lane >> 4) * 8]);
      #pragma unroll
      for (int mf = 0; mf < 4; mf++)
        #pragma unroll
        for (int nf = 0; nf < 4; nf++) {
          uint32_t bb[2] = { bF[nf >> 1][nf & 1], bF[nf >> 1][(nf & 1) + 2] };
          mma16816(acc[mf][nf], aF[mf], bb);
        }
    }
  }

  #pragma unroll
  for (int mf = 0; mf < 4; mf++) {
    int row0 = bm + wm + mf * 16 + (lane >> 2);
    #pragma unroll
    for (int nf = 0; nf < 4; nf++) {
      int col = bn + wn + nf * 8 + (lane & 3) * 2;
      float bb0 = bias[col], bb1 = bias[col + 1];
      #pragma unroll
      for (int h = 0; h < 2; h++) {
        int row = row0 + h * 8;
        float v0 = acc[mf][nf][h * 2 + 0] + bb0;
        float v1 = acc[mf][nf][h * 2 + 1] + bb1;
        if (mode == 0) {
          *(float2*)(outp + (size_t)row * 1024 + col) = make_float2(v0, v1);
        } else {
          int b = row >> 11, t = row & (Tc - 1), hh = col >> 6, d = col & 63;
          size_t base = ((size_t)(b * Hc + hh) * Tc + t) * 64 + d;
          if (mode == 3) {
            *(float2*)(g_V + base) = make_float2(v0, v1);
          } else {
            __half2 hv = __floats2half2_rn(v0, v1);
            *(__half2*)((mode == 1 ? g_QH : g_KH) + base) = hv;
          }
        }
      }
    }
  }
}

// ---------------- scores: E = exp(QK^T/8); Es OVERLAYS Qs/Ks ----------------
// dyn smem: Qs[128][72] @0, Ks[128][72] @9216 (36864 B total).
// After MMA, Es[128][136] (34816 B) overlays the same region.
__global__ __launch_bounds__(256, 2)
void score_tc(int bh0)
{
  int p = blockIdx.x;
  int qt = (int)((sqrtf(8.0f * p + 1.0f) - 1.0f) * 0.5f);
  while ((qt + 1) * (qt + 2) / 2 <= p) qt++;
  while (qt * (qt + 1) / 2 > p) qt--;
  const int kt = p - qt * (qt + 1) / 2;
  const int bh = bh0 + blockIdx.y;

  extern __shared__ __align__(16) __half sm[];
  __half (*Qs)[72]  = (__half(*)[72])(sm);
  __half (*Ks)[72]  = (__half(*)[72])(sm + 9216);
  __half (*Es)[136] = (__half(*)[136])(sm);      // overlay after MMA
  __shared__ float cs2[2][128];
  const int tid = threadIdx.x, lane = tid & 31, wid = tid >> 5;
  const int wm = (wid >> 2) * 64, wn = (wid & 3) * 32;
  const size_t hb = (size_t)bh * Tc * 64;

  #pragma unroll
  for (int i = 0; i < 4; i++) {
    int u = tid + i * 256, r = u >> 3, c = u & 7;
    cpa16(&Qs[r][c * 8], g_QH + hb + (size_t)(qt * 128 + r) * 64 + c * 8);
    cpa16(&Ks[r][c * 8], g_KH + hb + (size_t)(kt * 128 + r) * 64 + c * 8);
  }
  CP_COMMIT();
  CP_WAIT0();
  __syncthreads();

  float acc[4][4][4] = {};
  #pragma unroll
  for (int k16 = 0; k16 < 4; k16++) {
    uint32_t aF[4][4], bF[2][4];
    #pragma unroll
    for (int mf = 0; mf < 4; mf++)
      ldsm4(aF[mf], &Qs[wm + mf * 16 + (lane & 15)][k16 * 16 + (lane >> 4) * 8]);
    #pragma unroll
    for (int nh = 0; nh < 2; nh++)
      ldsm4(bF[nh], &Ks[wn + nh * 16 + (lane & 15)][k16 * 16 + (lane >> 4) * 8]);
    #pragma unroll
    for (int mf = 0; mf < 4; mf++)
      #pragma unroll
      for (int nf = 0; nf < 4; nf++) {
        uint32_t bb[2] = { bF[nf >> 1][nf & 1], bF[nf >> 1][(nf & 1) + 2] };
        mma16816(acc[mf][nf], aF[mf], bb);
      }
  }
  __syncthreads();   // all warps done reading Qs/Ks before Es overlay

  if (kt == qt) {
    #pragma unroll
    for (int mf = 0; mf < 4; mf++) {
      #pragma unroll
      for (int nf = 0; nf < 4; nf++) {
        int klocal = wn + nf * 8 + (lane & 3) * 2;
        #pragma unroll
        for (int h = 0; h < 2; h++) {
          int rloc = wm + mf * 16 + (lane >> 2) + h * 8;
          float e0 = (klocal     <= rloc) ? __expf(acc[mf][nf][h*2+0] * 0.125f) : 0.0f;
          float e1 = (klocal + 1 <= rloc) ? __expf(acc[mf][nf][h*2+1] * 0.125f) : 0.0f;
          *(__half2*)&Es[rloc][klocal] = __floats2half2_rn(e0, e1);
        }
      }
    }
  } else {
    #pragma unroll
    for (int mf = 0; mf < 4; mf++) {
      #pragma unroll
      for (int nf = 0; nf < 4; nf++) {
        int klocal = wn + nf * 8 + (lane & 3) * 2;
        #pragma unroll
        for (int h = 0; h < 2; h++) {
          int rloc = wm + mf * 16 + (lane >> 2) + h * 8;
          float e0 = __expf(acc[mf][nf][h*2+0] * 0.125f);
          float e1 = __expf(acc[mf][nf][h*2+1] * 0.125f);
          *(__half2*)&Es[rloc][klocal] = __floats2half2_rn(e0, e1);
        }
      }
    }
  }
  __syncthreads();

  #pragma unroll
  for (int i = 0; i < 8; i++) {
    int u = tid + i * 256, r = u >> 4, c = u & 15;
    *(uint4*)(g_E + ((size_t)bh * Tc + qt * 128 + r) * Tc + kt * 128 + c * 8) =
      *(const uint4*)&Es[r][c * 8];
  }
  {
    const int col = tid & 127, hf = tid >> 7;
    float s = 0.0f;
    #pragma unroll 8
    for (int r = 0; r < 64; r++) s += __half2float(Es[hf * 64 + r][col]);
    cs2[hf][col] = s;
  }
  __syncthreads();
  if (tid < 128)
    g_part[(bh * 16 + qt) * Tc + kt * 128 + tid] = cs2[0][tid] + cs2[1][tid];
}

// ---------------- fused: inv[k] from partials + VT = fp16(V * inv), transp --
__global__ __launch_bounds__(256)
void colsum_vtrans(int bh0)
{
  const int bh = bh0 + blockIdx.y, k0 = blockIdx.x * 64;
  __shared__ float inv_s[64];
  __shared__ float ts[64][65];
  const int tid = threadIdx.x, dl = tid & 63, kq = tid >> 6;

  if (tid < 64) {
    int k = k0 + tid;
    float s = 0.0f;
    for (int qt = k >> 7; qt < 16; qt++)
      s += g_part[(bh * 16 + qt) * Tc + k];
    inv_s[tid] = 1.0f / s;
  }
  __syncthreads();
  #pragma unroll
  for (int i = 0; i < 16; i++) {
    int kk = i * 4 + kq;
    ts[kk][dl] = g_V[((size_t)bh * Tc + k0 + kk) * 64 + dl] * inv_s[kk];
  }
  __syncthreads();
  #pragma unroll
  for (int i = 0; i < 16; i++) {
    int d = i * 4 + kq;
    g_VT[((size_t)bh * 64 + d) * Tc + k0 + dl] = __float2half(ts[dl][d]);
  }
}

// ---------------- O = E @ V' : 3-stage cp.async, ONE sync per chunk ---------
#define ASTG 13824
__global__ __launch_bounds__(256)
void attnv_tc(int bh0)
{
  extern __shared__ __align__(16) __half sm2[];
  const int qt = (int)gridDim.x - 1 - (int)blockIdx.x;   // longest first
  const int bh = bh0 + blockIdx.y;
  const int tid = threadIdx.x, lane = tid & 31, wid = tid >> 5;
  const int wm = (wid >> 1) * 32, wn = (wid & 1) * 32;
  const __half* Ep = g_E  + (size_t)bh * Tc * Tc;
  const __half* Vp = g_VT + (size_t)bh * 64 * Tc;

  #define AES(b) ((__half(*)[72])(sm2 + (b) * ASTG))
  #define AVS(b) ((__half(*)[72])(sm2 + (b) * ASTG + 9216))

  #define ALOAD(st, kb) do {                                                   \
    __half (*Es_)[72] = AES(st); __half (*Vs_)[72] = AVS(st);                  \
    _Pragma("unroll")                                                          \
    for (int i_ = 0; i_ < 4; i_++) {                                           \
      int u_ = tid + i_ * 256, r_ = u_ >> 3, c_ = u_ & 7;                      \
      cpa16(&Es_[r_][c_ * 8], Ep + (size_t)(qt * 128 + r_) * Tc + (kb) + c_ * 8); \
    }                                                                          \
    _Pragma("unroll")                                                          \
    for (int i_ = 0; i_ < 2; i_++) {                                           \
      int u_ = tid + i_ * 256, r_ = u_ >> 3, c_ = u_ & 7;                      \
      cpa16(&Vs_[r_][c_ * 8], Vp + (size_t)r_ * Tc + (kb) + c_ * 8);           \
    }                                                                          \
    CP_COMMIT();                                                               \
  } while (0)

  const int nch = (qt + 1) * 2;
  ALOAD(0, 0);
  if (nch > 1) ALOAD(1, 64);

  float acc[2][4][4] = {};
  for (int ch = 0; ch < nch; ch++) {
    if (ch + 1 < nch) CP_WAIT1(); else CP_WAIT0();
    __syncthreads();
    if (ch + 2 < nch) ALOAD((ch + 2) % 3, (ch + 2) * 64);
    __half (*Es)[72] = AES(ch % 3);
    __half (*Vs)[72] = AVS(ch % 3);
    #pragma unroll
    for (int k16 = 0; k16 < 4; k16++) {
      uint32_t aF[2][4], bF[2][4];
      #pragma unroll
      for (int mf = 0; mf < 2; mf++)
        ldsm4(aF[mf], &Es[wm + mf * 16 + (lane & 15)][k16 * 16 + (lane >> 4) * 8]);
      #pragma unroll
      for (int nh = 0; nh < 2; nh++)
        ldsm4(bF[nh], &Vs[wn + nh * 16 + (lane & 15)][k16 * 16 + (lane >> 4) * 8]);
      #pragma unroll
      for (int mf = 0; mf < 2; mf++)
        #pragma unroll
        for (int nf = 0; nf < 4; nf++) {
          uint32_t bb[2] = { bF[nf >> 1][nf & 1], bF[nf >> 1][(nf & 1) + 2] };
          mma16816(acc[mf][nf], aF[mf], bb);
        }
    }
  }

  const int b = bh >> 4, h = bh & 15;
  #pragma unroll
  for (int mf = 0; mf < 2; mf++) {
    #pragma unroll
    for (int nf = 0; nf < 4; nf++) {
      int d = wn + nf * 8 + (lane & 3) * 2;
      #pragma unroll
      for (int hh = 0; hh < 2; hh++) {
        int q = qt * 128 + wm + mf * 16 + (lane >> 2) + hh * 8;
        __half2 hv = __floats2half2_rn(acc[mf][nf][hh*2+0], acc[mf][nf][hh*2+1]);
        *(__half2*)(g_Xin + ((size_t)(b * Tc + q)) * 1024 + h * 64 + d) = hv;
      }
    }
  }
}

// ---------------------------------------------------------------------------
extern "C" void kernel_launch(void* const* d_in, const int* in_sizes, int n_in,
                              void* d_out, int out_size)
{
  const float* q  = (const float*)d_in[0];
  const float* k  = (const float*)d_in[1];
  const float* v  = (const float*)d_in[2];
  const float* Wq = (const float*)d_in[3];
  const float* bq = (const float*)d_in[4];
  const float* Wk = (const float*)d_in[5];
  const float* bk = (const float*)d_in[6];
  const float* Wv = (const float*)d_in[7];
  const float* bv = (const float*)d_in[8];
  const float* Wc = (const float*)d_in[9];
  const float* bc = (const float*)d_in[10];
  float* out = (float*)d_out;

  __half *pX, *pW;
  cudaGetSymbolAddress((void**)&pX, g_Xin);
  cudaGetSymbolAddress((void**)&pW, g_Wall);

  const int PR_SMEM = PSTG * 3 * 2;                    // 61440 B
  const int SC_SMEM = 36864;                           // Qs+Ks (Es overlays)
  const int AV_SMEM = ASTG * 3 * 2;                    // 82944 B
  cudaFuncSetAttribute(proj_tc,  cudaFuncAttributeMaxDynamicSharedMemorySize, PR_SMEM);
  cudaFuncSetAttribute(score_tc, cudaFuncAttributeMaxDynamicSharedMemorySize, SC_SMEM);
  cudaFuncSetAttribute(attnv_tc, cudaFuncAttributeMaxDynamicSharedMemorySize, AV_SMEM);

  dim3 tpb(256);
  cudaStream_t s1 = g_ss.s1;

  // s0: cvt -> projQK -> score(A) -> [evV] colsum(A) -> attnv(A) -> projO(b0)
  //     -> [evB] projO(b1)
  // s1: [evA] projV -> [evSA] score(B) -> colsum(B) -> attnv(B) -> evB
  cvt_all<<<8192, tpb>>>(q, k, v, Wq, Wk, Wv, Wc);
  cudaEventRecord(g_ss.evA, 0);

  proj_tc<<<dim3(8, 32, 2), tpb, PR_SMEM>>>(pX, pW, bq, bk, 1, nullptr);     // Q,K

  cudaStreamWaitEvent(s1, g_ss.evA, 0);
  proj_tc<<<dim3(8, 32, 1), tpb, PR_SMEM, s1>>>(
      pX + 2u * 4194304, pW + 2u * 1048576, bv, bv, 3, nullptr);             // V
  cudaEventRecord(g_ss.evV, s1);

  score_tc<<<dim3(136, GBH), tpb, SC_SMEM>>>(0);                             // A
  cudaEventRecord(g_ss.evSA, 0);

  cudaStreamWaitEvent(s1, g_ss.evSA, 0);
  score_tc<<<dim3(136, GBH), tpb, SC_SMEM, s1>>>(GBH);                       // B

  cudaStreamWaitEvent(0, g_ss.evV, 0);
  colsum_vtrans<<<dim3(32, GBH), tpb>>>(0);
  attnv_tc<<<dim3(16, GBH), tpb, AV_SMEM>>>(0);

  colsum_vtrans<<<dim3(32, GBH), tpb, 0, s1>>>(GBH);
  attnv_tc<<<dim3(16, GBH), tpb, AV_SMEM, s1>>>(GBH);
  cudaEventRecord(g_ss.evB, s1);

  // batch-0 output projection overlaps group B's attention
  proj_tc<<<dim3(8, 16, 1), tpb, PR_SMEM>>>(pX, pW + 3u * 1048576, bc, bc, 0, out);

  cudaStreamWaitEvent(0, g_ss.evB, 0);
  proj_tc<<<dim3(8, 16, 1), tpb, PR_SMEM>>>(
      pX + (size_t)Tc * 1024, pW + 3u * 1048576, bc, bc, 0, out + (size_t)Tc * 1024);
}

// round 15
// speedup vs baseline: 1.0220x; 1.0220x over previous
#include <cuda_runtime.h>
#include <cuda_fp16.h>
#include <stdint.h>

#define Tc  2048
#define Dc  1024
#define Hc  16
#define BHc 32
#define GBH 16                // heads per pipeline group (= one batch)

// ---------------- static device scratch ----------------
__device__ __half g_Xin[3u * 4194304];        // q,k,v fp16 (slot 0 reused for O)
__device__ __half g_Wall[4u * 1048576];       // Wq,Wk,Wv,Wc fp16
__device__ __half g_QH[BHc * Tc * 64];        // [bh][t][nd]
__device__ __half g_KH[BHc * Tc * 64];
__device__ float  g_V [BHc * Tc * 64];        // V heads fp32
__device__ __half g_VT[BHc * 64 * Tc];        // [bh][d][k], scaled by inv[k]
__device__ float  g_part[BHc * 16 * Tc];      // per-(bh,qt) column partials
__device__ __half g_E[(size_t)BHc * Tc * Tc]; // exp(z), fp16, lower tile-band

// ---------------- streams/events (host objects; created pre-main) ----------
namespace {
struct SideStream {
  cudaStream_t s1 = nullptr;
  cudaEvent_t evA = nullptr, evV = nullptr, evSA = nullptr, evB = nullptr;
  SideStream() {
    cudaStreamCreateWithFlags(&s1, cudaStreamNonBlocking);
    cudaEventCreateWithFlags(&evA,  cudaEventDisableTiming);
    cudaEventCreateWithFlags(&evV,  cudaEventDisableTiming);
    cudaEventCreateWithFlags(&evSA, cudaEventDisableTiming);
    cudaEventCreateWithFlags(&evB,  cudaEventDisableTiming);
  }
};
SideStream g_ss;
}

// ---------------- warp MMA / async helpers ----------------
static __device__ __forceinline__ void mma16816(float* d, const uint32_t* a,
                                                const uint32_t* b) {
  asm volatile(
    "mma.sync.aligned.m16n8k16.row.col.f32.f16.f16.f32 "
    "{%0,%1,%2,%3}, {%4,%5,%6,%7}, {%8,%9}, {%0,%1,%2,%3};"
    : "+f"(d[0]), "+f"(d[1]), "+f"(d[2]), "+f"(d[3])
    : "r"(a[0]), "r"(a[1]), "r"(a[2]), "r"(a[3]), "r"(b[0]), "r"(b[1]));
}
static __device__ __forceinline__ void ldsm4(uint32_t* r, const void* p) {
  uint32_t a = (uint32_t)__cvta_generic_to_shared(p);
  asm volatile("ldmatrix.sync.aligned.m8n8.x4.shared.b16 {%0,%1,%2,%3}, [%4];"
               : "=r"(r[0]), "=r"(r[1]), "=r"(r[2]), "=r"(r[3]) : "r"(a));
}
static __device__ __forceinline__ void cpa16(void* s, const void* g) {
  uint32_t a = (uint32_t)__cvta_generic_to_shared(s);
  asm volatile("cp.async.cg.shared.global [%0], [%1], 16;" :: "r"(a), "l"(g));
}
#define CP_COMMIT() asm volatile("cp.async.commit_group;" ::: "memory")
#define CP_WAIT1()  asm volatile("cp.async.wait_group 1;" ::: "memory")
#define CP_WAIT0()  asm volatile("cp.async.wait_group 0;" ::: "memory")

// ---------------- one-shot fp32 -> fp16 for all inputs + weights ------------
__global__ __launch_bounds__(256)
void cvt_all(const float* __restrict__ q, const float* __restrict__ k,
             const float* __restrict__ v, const float* __restrict__ Wq,
             const float* __restrict__ Wk, const float* __restrict__ Wv,
             const float* __restrict__ Wc)
{
  size_t t8 = ((size_t)blockIdx.x * 256 + threadIdx.x) * 8;
  const float* src; __half* dst;
  if (t8 < (3ull << 22)) {
    int i = (int)(t8 >> 22); size_t off = t8 & ((1ull << 22) - 1);
    src = (i == 0 ? q : i == 1 ? k : v) + off;
    dst = g_Xin + ((size_t)i << 22) + off;
  } else {
    size_t r = t8 - (3ull << 22);
    int w = (int)(r >> 20); size_t off = r & ((1ull << 20) - 1);
    src = (w == 0 ? Wq : w == 1 ? Wk : w == 2 ? Wv : Wc) + off;
    dst = g_Wall + ((size_t)w << 20) + off;
  }
  float4 a = *(const float4*)(src);
  float4 b = *(const float4*)(src + 4);
  __half2 h0 = __floats2half2_rn(a.x, a.y), h1 = __floats2half2_rn(a.z, a.w);
  __half2 h2 = __floats2half2_rn(b.x, b.y), h3 = __floats2half2_rn(b.z, b.w);
  uint4 u;
  u.x = *(uint32_t*)&h0; u.y = *(uint32_t*)&h1;
  u.z = *(uint32_t*)&h2; u.w = *(uint32_t*)&h3;
  *(uint4*)dst = u;
}

// ---------------- projection GEMM: Y = X @ W^T + b --------------------------
#define PSTG (128*40 + 128*40)            // halves per stage: 10240
__global__ __launch_bounds__(256, 2)
void proj_tc(const __half* __restrict__ Xbase, const __half* __restrict__ Wbase,
             const float* __restrict__ b0, const float* __restrict__ b1,
             int mode0, float* __restrict__ outp)
{
  extern __shared__ __align__(16) __half psm[];
  const int tid = threadIdx.x, lane = tid & 31, wid = tid >> 5;
  const int bn = blockIdx.x * 128, bm = blockIdx.y * 128;
  const int wm = (wid >> 2) * 64, wn = (wid & 3) * 32;

  const int z = blockIdx.z;
  const int mode = mode0 ? mode0 + z : 0;
  const __half* X = Xbase + ((size_t)z << 22);
  const __half* W = Wbase + ((size_t)z << 20);
  const float* bias = z ? b1 : b0;

  const int lr = tid >> 2, lc = tid & 3;

  #define PLOAD(st, kb) do {                                                   \
    __half (*As_)[40] = (__half(*)[40])(psm + (st) * PSTG);                    \
    __half (*Bs_)[40] = (__half(*)[40])(psm + (st) * PSTG + 128*40);           \
    _Pragma("unroll")                                                          \
    for (int i_ = 0; i_ < 2; i_++) {                                           \
      cpa16(&As_[lr + i_*64][lc*8], X + (size_t)(bm + lr + i_*64)*1024 + (kb) + lc*8); \
      cpa16(&Bs_[lr + i_*64][lc*8], W + (size_t)(bn + lr + i_*64)*1024 + (kb) + lc*8); \
    }                                                                          \
    CP_COMMIT();                                                               \
  } while (0)

  PLOAD(0, 0);
  PLOAD(1, 32);

  float acc[4][4][4] = {};
  for (int ch = 0; ch < 32; ch++) {
    if (ch + 1 < 32) CP_WAIT1(); else CP_WAIT0();
    __syncthreads();
    if (ch + 2 < 32) PLOAD((ch + 2) % 3, (ch + 2) * 32);
    __half (*As)[40] = (__half(*)[40])(psm + (ch % 3) * PSTG);
    __half (*Bs)[40] = (__half(*)[40])(psm + (ch % 3) * PSTG + 128*40);
    #pragma unroll
    for (int k16 = 0; k16 < 2; k16++) {
      uint32_t aF[4][4], bF[2][4];
      #pragma unroll
      for (int mf = 0; mf < 4; mf++)
        ldsm4(aF[mf], &As[wm + mf * 16 + (lane & 15)][k16 * 16 + (lane >> 4) * 8]);
      #pragma unroll
      for (int nh = 0; nh < 2; nh++)
        ldsm4(bF[nh], &Bs[wn + nh * 16 + (lane & 15)][k16 * 16 + (lane >> 4) * 8]);
      #pragma unroll
      for (int mf = 0; mf < 4; mf++)
        #pragma unroll
        for (int nf = 0; nf < 4; nf++) {
          uint32_t bb[2] = { bF[nf >> 1][nf & 1], bF[nf >> 1][(nf & 1) + 2] };
          mma16816(acc[mf][nf], aF[mf], bb);
        }
    }
  }

  #pragma unroll
  for (int mf = 0; mf < 4; mf++) {
    int row0 = bm + wm + mf * 16 + (lane >> 2);
    #pragma unroll
    for (int nf = 0; nf < 4; nf++) {
      int col = bn + wn + nf * 8 + (lane & 3) * 2;
      float bb0 = bias[col], bb1 = bias[col + 1];
      #pragma unroll
      for (int h = 0; h < 2; h++) {
        int row = row0 + h * 8;
        float v0 = acc[mf][nf][h * 2 + 0] + bb0;
        float v1 = acc[mf][nf][h * 2 + 1] + bb1;
        if (mode == 0) {
          *(float2*)(outp + (size_t)row * 1024 + col) = make_float2(v0, v1);
        } else {
          int b = row >> 11, t = row & (Tc - 1), hh = col >> 6, d = col & 63;
          size_t base = ((size_t)(b * Hc + hh) * Tc + t) * 64 + d;
          if (mode == 3) {
            *(float2*)(g_V + base) = make_float2(v0, v1);
          } else {
            __half2 hv = __floats2half2_rn(v0, v1);
            *(__half2*)((mode == 1 ? g_QH : g_KH) + base) = hv;
          }
        }
      }
    }
  }
}

// ---------------- scores: E = exp(QK^T/8); register-based column partials ---
// dyn smem: Qs[128][72] @0, Ks[128][72] @9216, Es[128][136] @18432 (halves)
__global__ __launch_bounds__(256)
void score_tc(int bh0)
{
  int p = blockIdx.x;
  int qt = (int)((sqrtf(8.0f * p + 1.0f) - 1.0f) * 0.5f);
  while ((qt + 1) * (qt + 2) / 2 <= p) qt++;
  while (qt * (qt + 1) / 2 > p) qt--;
  const int kt = p - qt * (qt + 1) / 2;
  const int bh = bh0 + blockIdx.y;

  extern __shared__ __align__(16) __half sm[];
  __half (*Qs)[72]  = (__half(*)[72])(sm);
  __half (*Ks)[72]  = (__half(*)[72])(sm + 9216);
  __half (*Es)[136] = (__half(*)[136])(sm + 18432);
  __shared__ float cs[16][128];
  const int tid = threadIdx.x, lane = tid & 31, wid = tid >> 5;
  const int wm = (wid >> 2) * 64, wn = (wid & 3) * 32;
  const size_t hb = (size_t)bh * Tc * 64;

  #pragma unroll
  for (int i = 0; i < 4; i++) {
    int u = tid + i * 256, r = u >> 3, c = u & 7;
    cpa16(&Qs[r][c * 8], g_QH + hb + (size_t)(qt * 128 + r) * 64 + c * 8);
    cpa16(&Ks[r][c * 8], g_KH + hb + (size_t)(kt * 128 + r) * 64 + c * 8);
  }
  CP_COMMIT();
  CP_WAIT0();
  __syncthreads();

  float acc[4][4][4] = {};
  #pragma unroll
  for (int k16 = 0; k16 < 4; k16++) {
    uint32_t aF[4][4], bF[2][4];
    #pragma unroll
    for (int mf = 0; mf < 4; mf++)
      ldsm4(aF[mf], &Qs[wm + mf * 16 + (lane & 15)][k16 * 16 + (lane >> 4) * 8]);
    #pragma unroll
    for (int nh = 0; nh < 2; nh++)
      ldsm4(bF[nh], &Ks[wn + nh * 16 + (lane & 15)][k16 * 16 + (lane >> 4) * 8]);
    #pragma unroll
    for (int mf = 0; mf < 4; mf++)
      #pragma unroll
      for (int nf = 0; nf < 4; nf++) {
        uint32_t bb[2] = { bF[nf >> 1][nf & 1], bF[nf >> 1][(nf & 1) + 2] };
        mma16816(acc[mf][nf], aF[mf], bb);
      }
  }

  float csp[4][2] = {};
  if (kt == qt) {
    #pragma unroll
    for (int mf = 0; mf < 4; mf++) {
      #pragma unroll
      for (int nf = 0; nf < 4; nf++) {
        int klocal = wn + nf * 8 + (lane & 3) * 2;
        #pragma unroll
        for (int h = 0; h < 2; h++) {
          int rloc = wm + mf * 16 + (lane >> 2) + h * 8;
          float e0 = (klocal     <= rloc) ? __expf(acc[mf][nf][h*2+0] * 0.125f) : 0.0f;
          float e1 = (klocal + 1 <= rloc) ? __expf(acc[mf][nf][h*2+1] * 0.125f) : 0.0f;
          *(__half2*)&Es[rloc][klocal] = __floats2half2_rn(e0, e1);
          csp[nf][0] += e0;
          csp[nf][1] += e1;
        }
      }
    }
  } else {
    #pragma unroll
    for (int mf = 0; mf < 4; mf++) {
      #pragma unroll
      for (int nf = 0; nf < 4; nf++) {
        int klocal = wn + nf * 8 + (lane & 3) * 2;
        #pragma unroll
        for (int h = 0; h < 2; h++) {
          int rloc = wm + mf * 16 + (lane >> 2) + h * 8;
          float e0 = __expf(acc[mf][nf][h*2+0] * 0.125f);
          float e1 = __expf(acc[mf][nf][h*2+1] * 0.125f);
          *(__half2*)&Es[rloc][klocal] = __floats2half2_rn(e0, e1);
          csp[nf][0] += e0;
          csp[nf][1] += e1;
        }
      }
    }
  }
  // stage register partials: cs[16][128], conflict-free
  {
    int rg = (wid >> 2) * 8 + (lane >> 2);
    #pragma unroll
    for (int nf = 0; nf < 4; nf++) {
      cs[rg][wn + nf * 8 + (lane & 3) * 2 + 0] = csp[nf][0];
      cs[rg][wn + nf * 8 + (lane & 3) * 2 + 1] = csp[nf][1];
    }
  }
  __syncthreads();

  #pragma unroll
  for (int i = 0; i < 8; i++) {
    int u = tid + i * 256, r = u >> 4, c = u & 15;
    *(uint4*)(g_E + ((size_t)bh * Tc + qt * 128 + r) * Tc + kt * 128 + c * 8) =
      *(const uint4*)&Es[r][c * 8];
  }
  if (tid < 128) {
    float s = 0.0f;
    #pragma unroll
    for (int i = 0; i < 16; i++) s += cs[i][tid];
    g_part[(bh * 16 + qt) * Tc + kt * 128 + tid] = s;
  }
}

// ---------------- fused: inv[k] from partials + VT = fp16(V * inv), transp --
__global__ __launch_bounds__(256)
void colsum_vtrans(int bh0)
{
  const int bh = bh0 + blockIdx.y, k0 = blockIdx.x * 64;
  __shared__ float inv_s[64];
  __shared__ float ts[64][65];
  const int tid = threadIdx.x, dl = tid & 63, kq = tid >> 6;

  if (tid < 64) {
    int k = k0 + tid;
    float s = 0.0f;
    for (int qt = k >> 7; qt < 16; qt++)
      s += g_part[(bh * 16 + qt) * Tc + k];
    inv_s[tid] = 1.0f / s;
  }
  __syncthreads();
  #pragma unroll
  for (int i = 0; i < 16; i++) {
    int kk = i * 4 + kq;
    ts[kk][dl] = g_V[((size_t)bh * Tc + k0 + kk) * 64 + dl] * inv_s[kk];
  }
  __syncthreads();
  #pragma unroll
  for (int i = 0; i < 16; i++) {
    int d = i * 4 + kq;
    g_VT[((size_t)bh * 64 + d) * Tc + k0 + dl] = __float2half(ts[dl][d]);
  }
}

// ---------------- O = E @ V' : 3-stage cp.async, ONE sync per chunk ---------
#define ASTG 13824
__global__ __launch_bounds__(256)
void attnv_tc(int bh0)
{
  extern __shared__ __align__(16) __half sm2[];
  const int qt = (int)gridDim.x - 1 - (int)blockIdx.x;   // longest first
  const int bh = bh0 + blockIdx.y;
  const int tid = threadIdx.x, lane = tid & 31, wid = tid >> 5;
  const int wm = (wid >> 1) * 32, wn = (wid & 1) * 32;
  const __half* Ep = g_E  + (size_t)bh * Tc * Tc;
  const __half* Vp = g_VT + (size_t)bh * 64 * Tc;

  #define AES(b) ((__half(*)[72])(sm2 + (b) * ASTG))
  #define AVS(b) ((__half(*)[72])(sm2 + (b) * ASTG + 9216))

  #define ALOAD(st, kb) do {                                                   \
    __half (*Es_)[72] = AES(st); __half (*Vs_)[72] = AVS(st);                  \
    _Pragma("unroll")                                                          \
    for (int i_ = 0; i_ < 4; i_++) {                                           \
      int u_ = tid + i_ * 256, r_ = u_ >> 3, c_ = u_ & 7;                      \
      cpa16(&Es_[r_][c_ * 8], Ep + (size_t)(qt * 128 + r_) * Tc + (kb) + c_ * 8); \
    }                                                                          \
    _Pragma("unroll")                                                          \
    for (int i_ = 0; i_ < 2; i_++) {                                           \
      int u_ = tid + i_ * 256, r_ = u_ >> 3, c_ = u_ & 7;                      \
      cpa16(&Vs_[r_][c_ * 8], Vp + (size_t)r_ * Tc + (kb) + c_ * 8);           \
    }                                                                          \
    CP_COMMIT();                                                               \
  } while (0)

  const int nch = (qt + 1) * 2;
  ALOAD(0, 0);
  if (nch > 1) ALOAD(1, 64);

  float acc[2][4][4] = {};
  for (int ch = 0; ch < nch; ch++) {
    if (ch + 1 < nch) CP_WAIT1(); else CP_WAIT0();
    __syncthreads();
    if (ch + 2 < nch) ALOAD((ch + 2) % 3, (ch + 2) * 64);
    __half (*Es)[72] = AES(ch % 3);
    __half (*Vs)[72] = AVS(ch % 3);
    #pragma unroll
    for (int k16 = 0; k16 < 4; k16++) {
      uint32_t aF[2][4], bF[2][4];
      #pragma unroll
      for (int mf = 0; mf < 2; mf++)
        ldsm4(aF[mf], &Es[wm + mf * 16 + (lane & 15)][k16 * 16 + (lane >> 4) * 8]);
      #pragma unroll
      for (int nh = 0; nh < 2; nh++)
        ldsm4(bF[nh], &Vs[wn + nh * 16 + (lane & 15)][k16 * 16 + (lane >> 4) * 8]);
      #pragma unroll
      for (int mf = 0; mf < 2; mf++)
        #pragma unroll
        for (int nf = 0; nf < 4; nf++) {
          uint32_t bb[2] = { bF[nf >> 1][nf & 1], bF[nf >> 1][(nf & 1) + 2] };
          mma16816(acc[mf][nf], aF[mf], bb);
        }
    }
  }

  const int b = bh >> 4, h = bh & 15;
  #pragma unroll
  for (int mf = 0; mf < 2; mf++) {
    #pragma unroll
    for (int nf = 0; nf < 4; nf++) {
      int d = wn + nf * 8 + (lane & 3) * 2;
      #pragma unroll
      for (int hh = 0; hh < 2; hh++) {
        int q = qt * 128 + wm + mf * 16 + (lane >> 2) + hh * 8;
        __half2 hv = __floats2half2_rn(acc[mf][nf][hh*2+0], acc[mf][nf][hh*2+1]);
        *(__half2*)(g_Xin + ((size_t)(b * Tc + q)) * 1024 + h * 64 + d) = hv;
      }
    }
  }
}

// ---------------------------------------------------------------------------
extern "C" void kernel_launch(void* const* d_in, const int* in_sizes, int n_in,
                              void* d_out, int out_size)
{
  const float* q  = (const float*)d_in[0];
  const float* k  = (const float*)d_in[1];
  const float* v  = (const float*)d_in[2];
  const float* Wq = (const float*)d_in[3];
  const float* bq = (const float*)d_in[4];
  const float* Wk = (const float*)d_in[5];
  const float* bk = (const float*)d_in[6];
  const float* Wv = (const float*)d_in[7];
  const float* bv = (const float*)d_in[8];
  const float* Wc = (const float*)d_in[9];
  const float* bc = (const float*)d_in[10];
  float* out = (float*)d_out;

  __half *pX, *pW;
  cudaGetSymbolAddress((void**)&pX, g_Xin);
  cudaGetSymbolAddress((void**)&pW, g_Wall);

  const int PR_SMEM = PSTG * 3 * 2;                    // 61440 B
  const int SC_SMEM = (9216 * 2 + 128 * 136) * 2;      // 71680 B
  const int AV_SMEM = ASTG * 3 * 2;                    // 82944 B
  cudaFuncSetAttribute(proj_tc,  cudaFuncAttributeMaxDynamicSharedMemorySize, PR_SMEM);
  cudaFuncSetAttribute(score_tc, cudaFuncAttributeMaxDynamicSharedMemorySize, SC_SMEM);
  cudaFuncSetAttribute(attnv_tc, cudaFuncAttributeMaxDynamicSharedMemorySize, AV_SMEM);

  dim3 tpb(256);
  cudaStream_t s1 = g_ss.s1;

  // s0: cvt -> projQK -> score(A) -> [evV] colsum(A) -> attnv(A) -> [evB] projO
  // s1: [evA] projV -> [evSA] score(B) -> colsum(B) -> attnv(B) -> evB
  cvt_all<<<8192, tpb>>>(q, k, v, Wq, Wk, Wv, Wc);
  cudaEventRecord(g_ss.evA, 0);

  proj_tc<<<dim3(8, 32, 2), tpb, PR_SMEM>>>(pX, pW, bq, bk, 1, nullptr);     // Q,K

  cudaStreamWaitEvent(s1, g_ss.evA, 0);
  proj_tc<<<dim3(8, 32, 1), tpb, PR_SMEM, s1>>>(
      pX + 2u * 4194304, pW + 2u * 1048576, bv, bv, 3, nullptr);             // V
  cudaEventRecord(g_ss.evV, s1);

  score_tc<<<dim3(136, GBH), tpb, SC_SMEM>>>(0);                             // A
  cudaEventRecord(g_ss.evSA, 0);

  cudaStreamWaitEvent(s1, g_ss.evSA, 0);
  score_tc<<<dim3(136, GBH), tpb, SC_SMEM, s1>>>(GBH);                       // B

  cudaStreamWaitEvent(0, g_ss.evV, 0);
  colsum_vtrans<<<dim3(32, GBH), tpb>>>(0);
  attnv_tc<<<dim3(16, GBH), tpb, AV_SMEM>>>(0);

  colsum_vtrans<<<dim3(32, GBH), tpb, 0, s1>>>(GBH);
  attnv_tc<<<dim3(16, GBH), tpb, AV_SMEM, s1>>>(GBH);
  cudaEventRecord(g_ss.evB, s1);

  cudaStreamWaitEvent(0, g_ss.evB, 0);
  proj_tc<<<dim3(8, 32, 1), tpb, PR_SMEM>>>(pX, pW + 3u * 1048576, bc, bc, 0, out);
}